// round 2
// baseline (speedup 1.0000x reference)
#include <cuda_runtime.h>
#include <math.h>

// ---------------------------------------------------------------------------
// Scratch (max intermediate: conv1 out = 16*96*15*15 = 345600 floats / variant)
// ---------------------------------------------------------------------------
#define VS 345600
__device__ float g_bufA[3 * VS];
__device__ float g_bufB[3 * VS];

__device__ __forceinline__ float root8(float s) {
    // s >= 0 always; s^(1/8) = sqrt(sqrt(sqrt(s)))
    return sqrtf(sqrtf(sqrtf(s)));
}

// ---------------------------------------------------------------------------
// NormDist (L8-distance) conv with interval bounds.
// One warp computes one (b, oy, ox) position for 4 consecutive output
// channels; lanes partition the reduction dim F = C*K*K.
// Out-of-bounds (padding) contributes value 0 => distance |w| (matches ref).
// ---------------------------------------------------------------------------
template<int K>
__global__ void __launch_bounds__(256) normdist_conv_kernel(
    const float* __restrict__ inc, const float* __restrict__ inl, const float* __restrict__ inh,
    const float* __restrict__ wgt,
    float* __restrict__ outc, float* __restrict__ outl, float* __restrict__ outh,
    int B, int C, int H, int W, int O, int Ho, int Wo, int S, int pad)
{
    const int warp = (blockIdx.x * blockDim.x + threadIdx.x) >> 5;
    const int lane = threadIdx.x & 31;
    const int L = Ho * Wo;
    const int OG = O >> 2;
    if (warp >= B * OG * L) return;

    const int l  = warp % L;
    const int t  = warp / L;
    const int og = t % OG;
    const int b  = t / OG;
    const int oy = l / Wo, ox = l % Wo;
    const int y0 = oy * S - pad, x0 = ox * S - pad;
    const int F  = C * K * K;

    const size_t ib = (size_t)b * C * H * W;
    const float* pc = inc + ib;
    const float* pl = inl + ib;
    const float* ph = inh + ib;
    const float* w0 = wgt + (size_t)(og * 4) * F;

    float ac0 = 0.f, ac1 = 0.f, ac2 = 0.f, ac3 = 0.f;
    float al0 = 0.f, al1 = 0.f, al2 = 0.f, al3 = 0.f;
    float ah0 = 0.f, ah1 = 0.f, ah2 = 0.f, ah3 = 0.f;

    for (int f = lane; f < F; f += 32) {
        const int c  = f / (K * K);
        const int r  = f - c * (K * K);
        const int ky = r / K;
        const int kx = r - ky * K;
        const int iy = y0 + ky, ix = x0 + kx;
        float vc = 0.f, vl = 0.f, vh = 0.f;
        if ((unsigned)iy < (unsigned)H && (unsigned)ix < (unsigned)W) {
            const int idx = (c * H + iy) * W + ix;
            vc = pc[idx]; vl = pl[idx]; vh = ph[idx];
        }
#define ND_ACC(WV, AC, AL, AH) {                                   \
        const float wv = (WV);                                     \
        float dc = fabsf(vc - wv);                                  \
        float a  = vl - wv;                                         \
        float bb = wv - vh;                                         \
        float dl = fmaxf(fmaxf(a, bb), 0.f);                        \
        float dh = fmaxf(fabsf(a), fabsf(bb));                      \
        float t2 = dc * dc; t2 = t2 * t2; AC = fmaf(t2, t2, AC);    \
        float u2 = dl * dl; u2 = u2 * u2; AL = fmaf(u2, u2, AL);    \
        float v2 = dh * dh; v2 = v2 * v2; AH = fmaf(v2, v2, AH); }
        ND_ACC(w0[f],         ac0, al0, ah0);
        ND_ACC(w0[F + f],     ac1, al1, ah1);
        ND_ACC(w0[2 * F + f], ac2, al2, ah2);
        ND_ACC(w0[3 * F + f], ac3, al3, ah3);
#undef ND_ACC
    }

#pragma unroll
    for (int off = 16; off; off >>= 1) {
        ac0 += __shfl_xor_sync(0xffffffffu, ac0, off);
        ac1 += __shfl_xor_sync(0xffffffffu, ac1, off);
        ac2 += __shfl_xor_sync(0xffffffffu, ac2, off);
        ac3 += __shfl_xor_sync(0xffffffffu, ac3, off);
        al0 += __shfl_xor_sync(0xffffffffu, al0, off);
        al1 += __shfl_xor_sync(0xffffffffu, al1, off);
        al2 += __shfl_xor_sync(0xffffffffu, al2, off);
        al3 += __shfl_xor_sync(0xffffffffu, al3, off);
        ah0 += __shfl_xor_sync(0xffffffffu, ah0, off);
        ah1 += __shfl_xor_sync(0xffffffffu, ah1, off);
        ah2 += __shfl_xor_sync(0xffffffffu, ah2, off);
        ah3 += __shfl_xor_sync(0xffffffffu, ah3, off);
    }

    const size_t ob = ((size_t)b * O + (size_t)og * 4) * L + l;
    if (lane == 0) {
        outc[ob] = root8(ac0); outl[ob] = root8(al0); outh[ob] = root8(ah0);
    } else if (lane == 1) {
        outc[ob + L] = root8(ac1); outl[ob + L] = root8(al1); outh[ob + L] = root8(ah1);
    } else if (lane == 2) {
        outc[ob + 2 * L] = root8(ac2); outl[ob + 2 * L] = root8(al2); outh[ob + 2 * L] = root8(ah2);
    } else if (lane == 3) {
        outc[ob + 3 * L] = root8(ac3); outl[ob + 3 * L] = root8(al3); outh[ob + 3 * L] = root8(ah3);
    }
}

// ---------------------------------------------------------------------------
// 3x3 / stride-2 maxpool on all three bound tensors at once.
// ---------------------------------------------------------------------------
__global__ void __launch_bounds__(256) maxpool_kernel(
    const float* __restrict__ i0, const float* __restrict__ i1, const float* __restrict__ i2,
    float* __restrict__ o0, float* __restrict__ o1, float* __restrict__ o2,
    int NC, int H, int W, int h, int w)
{
    const int i = blockIdx.x * blockDim.x + threadIdx.x;
    if (i >= NC * h * w) return;
    const int x = i % w;
    const int y = (i / w) % h;
    const int n = i / (w * h);
    const int base = (n * H + y * 2) * W + x * 2;
    float m0 = -3.402823466e38f, m1 = m0, m2 = m0;
#pragma unroll
    for (int ky = 0; ky < 3; ky++) {
#pragma unroll
        for (int kx = 0; kx < 3; kx++) {
            const int idx = base + ky * W + kx;
            m0 = fmaxf(m0, i0[idx]);
            m1 = fmaxf(m1, i1[idx]);
            m2 = fmaxf(m2, i2[idx]);
        }
    }
    o0[i] = m0; o1[i] = m1; o2[i] = m2;
}

// ---------------------------------------------------------------------------
// Interval-bound linear: oc = c@W^T (+b); mid = 0.5(l+h)@W^T (+b);
// rad = 0.5(h-l)@|W|^T; ol = mid-rad; oh = mid+rad.
// Warp per (b, o); lanes process float4 chunks of the input dim.
// mode 0: relu epilogue; mode 1: final layer (write -c, -u, -l).
// ---------------------------------------------------------------------------
__global__ void __launch_bounds__(256) bound_linear_kernel(
    const float* __restrict__ inc, const float* __restrict__ inl, const float* __restrict__ inh,
    const float* __restrict__ Wm, const float* __restrict__ bias,
    float* __restrict__ outc, float* __restrict__ outl, float* __restrict__ outh,
    int B, int IN, int OUT, int mode)
{
    const int warp = (blockIdx.x * blockDim.x + threadIdx.x) >> 5;
    const int lane = threadIdx.x & 31;
    if (warp >= B * OUT) return;
    const int o = warp % OUT;
    const int b = warp / OUT;

    const float4* c4 = (const float4*)(inc + (size_t)b * IN);
    const float4* l4 = (const float4*)(inl + (size_t)b * IN);
    const float4* h4 = (const float4*)(inh + (size_t)b * IN);
    const float4* w4 = (const float4*)(Wm + (size_t)o * IN);
    const int n4 = IN >> 2;

    float sc = 0.f, sm = 0.f, sr = 0.f;
    for (int k = lane; k < n4; k += 32) {
        const float4 cv = c4[k], lv = l4[k], hv = h4[k], wv = w4[k];
        sc = fmaf(cv.x, wv.x, sc); sc = fmaf(cv.y, wv.y, sc);
        sc = fmaf(cv.z, wv.z, sc); sc = fmaf(cv.w, wv.w, sc);
        sm = fmaf(lv.x + hv.x, wv.x, sm); sm = fmaf(lv.y + hv.y, wv.y, sm);
        sm = fmaf(lv.z + hv.z, wv.z, sm); sm = fmaf(lv.w + hv.w, wv.w, sm);
        sr = fmaf(hv.x - lv.x, fabsf(wv.x), sr); sr = fmaf(hv.y - lv.y, fabsf(wv.y), sr);
        sr = fmaf(hv.z - lv.z, fabsf(wv.z), sr); sr = fmaf(hv.w - lv.w, fabsf(wv.w), sr);
    }
#pragma unroll
    for (int off = 16; off; off >>= 1) {
        sc += __shfl_xor_sync(0xffffffffu, sc, off);
        sm += __shfl_xor_sync(0xffffffffu, sm, off);
        sr += __shfl_xor_sync(0xffffffffu, sr, off);
    }
    if (lane == 0) {
        const float bv  = bias ? bias[o] : 0.f;
        const float oc  = sc + bv;
        const float mid = 0.5f * sm + bv;
        const float rad = 0.5f * sr;
        const float ol  = mid - rad;
        const float oh  = mid + rad;
        const size_t idx = (size_t)b * OUT + o;
        if (mode == 0) {
            outc[idx] = fmaxf(oc, 0.f);
            outl[idx] = fmaxf(ol, 0.f);
            outh[idx] = fmaxf(oh, 0.f);
        } else {
            // reference returns (-c, -u, -l)
            outc[idx] = -oc;   // slot 0: -center
            outl[idx] = -oh;   // slot 1: -upper
            outh[idx] = -ol;   // slot 2: -lower
        }
    }
}

// ---------------------------------------------------------------------------
// Host-side orchestration (graph-capturable: kernel launches only).
// ---------------------------------------------------------------------------
static inline int conv_blocks(int B, int O, int L) {
    int warps = B * (O >> 2) * L;
    return (warps * 32 + 255) / 256;
}

extern "C" void kernel_launch(void* const* d_in, const int* in_sizes, int n_in,
                              void* d_out, int out_size)
{
    const float* x   = (const float*)d_in[0];
    const float* lo  = (const float*)d_in[1];
    const float* hi  = (const float*)d_in[2];
    const float* w1  = (const float*)d_in[3];
    const float* w2  = (const float*)d_in[4];
    const float* w3  = (const float*)d_in[5];
    const float* w4  = (const float*)d_in[6];
    const float* w5  = (const float*)d_in[7];
    const float* fw1 = (const float*)d_in[8];
    const float* fw2 = (const float*)d_in[9];
    const float* fw3 = (const float*)d_in[10];
    const float* fb3 = (const float*)d_in[11];
    float* out = (float*)d_out;

    float *A, *Bf;
    cudaGetSymbolAddress((void**)&A,  g_bufA);
    cudaGetSymbolAddress((void**)&Bf, g_bufB);
    float *Ac = A,  *Al = A  + VS, *Ah = A  + 2 * VS;
    float *Bc = Bf, *Bl = Bf + VS, *Bh = Bf + 2 * VS;

    // conv1: [16,3,32,32] -> [16,96,15,15]   (k=7, s=2, pad=2)
    normdist_conv_kernel<7><<<conv_blocks(16, 96, 225), 256>>>(
        x, lo, hi, w1, Ac, Al, Ah, 16, 3, 32, 32, 96, 15, 15, 2, 2);

    // pool1: 15 -> 7
    {
        int tot = 16 * 96 * 7 * 7;
        maxpool_kernel<<<(tot + 255) / 256, 256>>>(Ac, Al, Ah, Bc, Bl, Bh, 16 * 96, 15, 15, 7, 7);
    }

    // conv2: [16,96,7,7] -> [16,256,7,7]     (k=5, s=1, pad=2)
    normdist_conv_kernel<5><<<conv_blocks(16, 256, 49), 256>>>(
        Bc, Bl, Bh, w2, Ac, Al, Ah, 16, 96, 7, 7, 256, 7, 7, 1, 2);

    // pool2: 7 -> 3
    {
        int tot = 16 * 256 * 3 * 3;
        maxpool_kernel<<<(tot + 255) / 256, 256>>>(Ac, Al, Ah, Bc, Bl, Bh, 16 * 256, 7, 7, 3, 3);
    }

    // conv3: [16,256,3,3] -> [16,384,3,3]    (k=3, s=1, pad=1)
    normdist_conv_kernel<3><<<conv_blocks(16, 384, 9), 256>>>(
        Bc, Bl, Bh, w3, Ac, Al, Ah, 16, 256, 3, 3, 384, 3, 3, 1, 1);

    // conv4: [16,384,3,3] -> [16,384,3,3]
    normdist_conv_kernel<3><<<conv_blocks(16, 384, 9), 256>>>(
        Ac, Al, Ah, w4, Bc, Bl, Bh, 16, 384, 3, 3, 384, 3, 3, 1, 1);

    // conv5: [16,384,3,3] -> [16,256,3,3]
    normdist_conv_kernel<3><<<conv_blocks(16, 256, 9), 256>>>(
        Bc, Bl, Bh, w5, Ac, Al, Ah, 16, 384, 3, 3, 256, 3, 3, 1, 1);

    // fc1: 2304 -> 1024 (+relu)
    {
        int warps = 16 * 1024;
        bound_linear_kernel<<<(warps * 32 + 255) / 256, 256>>>(
            Ac, Al, Ah, fw1, (const float*)nullptr, Bc, Bl, Bh, 16, 2304, 1024, 0);
    }
    // fc2: 1024 -> 512 (+relu)
    {
        int warps = 16 * 512;
        bound_linear_kernel<<<(warps * 32 + 255) / 256, 256>>>(
            Bc, Bl, Bh, fw2, (const float*)nullptr, Ac, Al, Ah, 16, 1024, 512, 0);
    }
    // fc3: 512 -> 10 (+bias), final negate/swap -> d_out = [-c | -u | -l]
    {
        int warps = 16 * 10;
        bound_linear_kernel<<<(warps * 32 + 255) / 256, 256>>>(
            Ac, Al, Ah, fw3, fb3, out, out + 160, out + 320, 16, 512, 10, 1);
    }
}

// round 3
// speedup vs baseline: 1.7409x; 1.7409x over previous
#include <cuda_runtime.h>
#include <math.h>

typedef unsigned long long ull;

// ---------------------------------------------------------------------------
// Scratch buffers (device globals; no allocations allowed).
// VS: max layer output per bound tensor = conv1 out 16*96*15*15 = 345600.
// PS: max im2col patch size per tensor = conv2: 16*49*2400 = 1,881,600.
// ---------------------------------------------------------------------------
#define VS 345600
#define PS 1881600
__device__ float g_bufA[3 * VS];
__device__ float g_bufB[3 * VS];
__device__ float g_patch[3 * PS];
__device__ float g_wpad[96 * 148];

// ---------------------------------------------------------------------------
// f32x2 packed helpers (sm_103a)
// ---------------------------------------------------------------------------
__device__ __forceinline__ ull pk2(float lo, float hi) {
    ull r; asm("mov.b64 %0, {%1,%2};" : "=l"(r) : "f"(lo), "f"(hi)); return r;
}
__device__ __forceinline__ void upk2(ull v, float& lo, float& hi) {
    asm("mov.b64 {%0,%1}, %2;" : "=f"(lo), "=f"(hi) : "l"(v));
}
__device__ __forceinline__ ull fma2(ull a, ull b, ull c) {
    ull r; asm("fma.rn.f32x2 %0, %1, %2, %3;" : "=l"(r) : "l"(a), "l"(b), "l"(c)); return r;
}
__device__ __forceinline__ ull mul2(ull a, ull b) {
    ull r; asm("mul.rn.f32x2 %0, %1, %2;" : "=l"(r) : "l"(a), "l"(b)); return r;
}

__device__ __forceinline__ float root8(float s) {
    return sqrtf(sqrtf(sqrtf(s)));  // s >= 0 always
}

// ---------------------------------------------------------------------------
// im2col for the three bound tensors at once, with F padded to Fp (zeros).
// Layout: patch[(b*L + l)*Fp + f], f = c*K*K + ky*K + kx (torch-unfold order).
// ---------------------------------------------------------------------------
__global__ void __launch_bounds__(256) im2col_kernel(
    const float* __restrict__ ic, const float* __restrict__ il, const float* __restrict__ ih,
    float* __restrict__ oc, float* __restrict__ ol, float* __restrict__ oh,
    int B, int C, int H, int W, int K, int S, int pad, int Ho, int Wo, int Fp)
{
    const int idx = blockIdx.x * blockDim.x + threadIdx.x;
    const int L = Ho * Wo;
    const int F = C * K * K;
    if (idx >= B * L * Fp) return;
    const int f  = idx % Fp;
    const int bl = idx / Fp;
    const int l  = bl % L;
    const int b  = bl / L;
    float vc = 0.f, vl = 0.f, vh = 0.f;
    if (f < F) {
        const int c  = f / (K * K);
        const int r  = f - c * (K * K);
        const int ky = r / K, kx = r - (r / K) * K;
        const int oy = l / Wo, ox = l - (l / Wo) * Wo;
        const int iy = oy * S - pad + ky;
        const int ix = ox * S - pad + kx;
        if ((unsigned)iy < (unsigned)H && (unsigned)ix < (unsigned)W) {
            const int si = ((b * C + c) * H + iy) * W + ix;
            vc = ic[si]; vl = il[si]; vh = ih[si];
        }
    }
    oc[idx] = vc; ol[idx] = vl; oh[idx] = vh;
}

// Pad conv1 weights F=147 -> Fp=148 with zeros.
__global__ void __launch_bounds__(256) wpad_kernel(
    const float* __restrict__ w, float* __restrict__ wp, int O, int F, int Fp)
{
    const int idx = blockIdx.x * blockDim.x + threadIdx.x;
    if (idx >= O * Fp) return;
    const int f = idx % Fp, o = idx / Fp;
    wp[idx] = (f < F) ? w[o * F + f] : 0.f;
}

// ---------------------------------------------------------------------------
// Packed NormDist (L8) conv on im2col patches.
// One warp -> one (b,l) x 4 output channels; lanes take float4 chunks of Fp.
// ---------------------------------------------------------------------------
__global__ void __launch_bounds__(256) normdist_conv_p_kernel(
    const float* __restrict__ pc, const float* __restrict__ pl, const float* __restrict__ ph,
    const float* __restrict__ wgt,
    float* __restrict__ outc, float* __restrict__ outl, float* __restrict__ outh,
    int BL, int OG, int Fp, int L, int O)
{
    const int warp = (blockIdx.x * blockDim.x + threadIdx.x) >> 5;
    const int lane = threadIdx.x & 31;
    if (warp >= BL * OG) return;
    const int og = warp % OG;
    const int bl = warp / OG;

    const int fs = Fp >> 2;  // row stride in float4
    const float4* pc4 = (const float4*)(pc + (size_t)bl * Fp);
    const float4* pl4 = (const float4*)(pl + (size_t)bl * Fp);
    const float4* ph4 = (const float4*)(ph + (size_t)bl * Fp);
    const float4* wp  = (const float4*)(wgt + (size_t)(og * 4) * Fp);

    const ull M1 = 0xBF800000BF800000ULL;  // (-1.0f, -1.0f)

    ull AC0 = 0, AL0 = 0, AH0 = 0;
    ull AC1 = 0, AL1 = 0, AH1 = 0;
    ull AC2 = 0, AL2 = 0, AH2 = 0;
    ull AC3 = 0, AL3 = 0, AH3 = 0;

#define PROC_HALF(W2, VC, VL, VH, AC, AL, AH) {                        \
        ull dc = fma2(W2, M1, VC);                                     \
        ull av = fma2(W2, M1, VL);                                     \
        ull bv = fma2(VH, M1, W2);                                     \
        ull s  = mul2(dc, dc); s = mul2(s, s); AC = fma2(s, s, AC);    \
        float a0, a1, b0, b1;                                          \
        upk2(av, a0, a1); upk2(bv, b0, b1);                            \
        float l0 = fmaxf(fmaxf(a0, b0), 0.f);                          \
        float l1 = fmaxf(fmaxf(a1, b1), 0.f);                          \
        ull dl = pk2(l0, l1);                                          \
        s = mul2(dl, dl); s = mul2(s, s); AL = fma2(s, s, AL);         \
        float h0 = fmaxf(fabsf(a0), fabsf(b0));                       \
        float h1 = fmaxf(fabsf(a1), fabsf(b1));                       \
        ull dh = pk2(h0, h1);                                          \
        s = mul2(dh, dh); s = mul2(s, s); AH = fma2(s, s, AH); }

#define PROC_CH(W4, AC, AL, AH) {                                      \
        ull w01 = pk2(W4.x, W4.y), w23 = pk2(W4.z, W4.w);              \
        PROC_HALF(w01, vc01, vl01, vh01, AC, AL, AH);                  \
        PROC_HALF(w23, vc23, vl23, vh23, AC, AL, AH); }

    for (int q = lane; q < fs; q += 32) {
        const float4 vc = pc4[q], vl = pl4[q], vh = ph4[q];
        const ull vc01 = pk2(vc.x, vc.y), vc23 = pk2(vc.z, vc.w);
        const ull vl01 = pk2(vl.x, vl.y), vl23 = pk2(vl.z, vl.w);
        const ull vh01 = pk2(vh.x, vh.y), vh23 = pk2(vh.z, vh.w);
        float4 w;
        w = wp[q];          PROC_CH(w, AC0, AL0, AH0);
        w = wp[q + fs];     PROC_CH(w, AC1, AL1, AH1);
        w = wp[q + 2 * fs]; PROC_CH(w, AC2, AL2, AH2);
        w = wp[q + 3 * fs]; PROC_CH(w, AC3, AL3, AH3);
    }
#undef PROC_CH
#undef PROC_HALF

    float r[12];
    {
        float x, y;
        upk2(AC0, x, y); r[0]  = x + y;  upk2(AL0, x, y); r[1]  = x + y;  upk2(AH0, x, y); r[2]  = x + y;
        upk2(AC1, x, y); r[3]  = x + y;  upk2(AL1, x, y); r[4]  = x + y;  upk2(AH1, x, y); r[5]  = x + y;
        upk2(AC2, x, y); r[6]  = x + y;  upk2(AL2, x, y); r[7]  = x + y;  upk2(AH2, x, y); r[8]  = x + y;
        upk2(AC3, x, y); r[9]  = x + y;  upk2(AL3, x, y); r[10] = x + y;  upk2(AH3, x, y); r[11] = x + y;
    }
#pragma unroll
    for (int off = 16; off; off >>= 1)
#pragma unroll
        for (int i = 0; i < 12; i++)
            r[i] += __shfl_xor_sync(0xffffffffu, r[i], off);

    if (lane < 4) {
        const int b = bl / L, l = bl - (bl / L) * L;
        const size_t ob = ((size_t)b * O + (size_t)og * 4 + lane) * L + l;
        outc[ob] = root8(r[3 * lane]);
        outl[ob] = root8(r[3 * lane + 1]);
        outh[ob] = root8(r[3 * lane + 2]);
    }
}

// ---------------------------------------------------------------------------
// 3x3 / stride-2 maxpool on all three bound tensors at once.
// ---------------------------------------------------------------------------
__global__ void __launch_bounds__(256) maxpool_kernel(
    const float* __restrict__ i0, const float* __restrict__ i1, const float* __restrict__ i2,
    float* __restrict__ o0, float* __restrict__ o1, float* __restrict__ o2,
    int NC, int H, int W, int h, int w)
{
    const int i = blockIdx.x * blockDim.x + threadIdx.x;
    if (i >= NC * h * w) return;
    const int x = i % w;
    const int y = (i / w) % h;
    const int n = i / (w * h);
    const int base = (n * H + y * 2) * W + x * 2;
    float m0 = -3.402823466e38f, m1 = m0, m2 = m0;
#pragma unroll
    for (int ky = 0; ky < 3; ky++)
#pragma unroll
        for (int kx = 0; kx < 3; kx++) {
            const int idx = base + ky * W + kx;
            m0 = fmaxf(m0, i0[idx]);
            m1 = fmaxf(m1, i1[idx]);
            m2 = fmaxf(m2, i2[idx]);
        }
    o0[i] = m0; o1[i] = m1; o2[i] = m2;
}

// ---------------------------------------------------------------------------
// Interval-bound linear. Warp per (b,o), float4 over input dim.
// mode 0: relu epilogue; mode 1: final layer (-c, -u, -l).
// ---------------------------------------------------------------------------
__global__ void __launch_bounds__(256) bound_linear_kernel(
    const float* __restrict__ inc, const float* __restrict__ inl, const float* __restrict__ inh,
    const float* __restrict__ Wm, const float* __restrict__ bias,
    float* __restrict__ outc, float* __restrict__ outl, float* __restrict__ outh,
    int B, int IN, int OUT, int mode)
{
    const int warp = (blockIdx.x * blockDim.x + threadIdx.x) >> 5;
    const int lane = threadIdx.x & 31;
    if (warp >= B * OUT) return;
    const int o = warp % OUT;
    const int b = warp / OUT;

    const float4* c4 = (const float4*)(inc + (size_t)b * IN);
    const float4* l4 = (const float4*)(inl + (size_t)b * IN);
    const float4* h4 = (const float4*)(inh + (size_t)b * IN);
    const float4* w4 = (const float4*)(Wm + (size_t)o * IN);
    const int n4 = IN >> 2;

    float sc = 0.f, sm = 0.f, sr = 0.f;
    for (int k = lane; k < n4; k += 32) {
        const float4 cv = c4[k], lv = l4[k], hv = h4[k], wv = w4[k];
        sc = fmaf(cv.x, wv.x, sc); sc = fmaf(cv.y, wv.y, sc);
        sc = fmaf(cv.z, wv.z, sc); sc = fmaf(cv.w, wv.w, sc);
        sm = fmaf(lv.x + hv.x, wv.x, sm); sm = fmaf(lv.y + hv.y, wv.y, sm);
        sm = fmaf(lv.z + hv.z, wv.z, sm); sm = fmaf(lv.w + hv.w, wv.w, sm);
        sr = fmaf(hv.x - lv.x, fabsf(wv.x), sr); sr = fmaf(hv.y - lv.y, fabsf(wv.y), sr);
        sr = fmaf(hv.z - lv.z, fabsf(wv.z), sr); sr = fmaf(hv.w - lv.w, fabsf(wv.w), sr);
    }
#pragma unroll
    for (int off = 16; off; off >>= 1) {
        sc += __shfl_xor_sync(0xffffffffu, sc, off);
        sm += __shfl_xor_sync(0xffffffffu, sm, off);
        sr += __shfl_xor_sync(0xffffffffu, sr, off);
    }
    if (lane == 0) {
        const float bv  = bias ? bias[o] : 0.f;
        const float oc  = sc + bv;
        const float mid = 0.5f * sm + bv;
        const float rad = 0.5f * sr;
        const size_t idx = (size_t)b * OUT + o;
        if (mode == 0) {
            outc[idx] = fmaxf(oc, 0.f);
            outl[idx] = fmaxf(mid - rad, 0.f);
            outh[idx] = fmaxf(mid + rad, 0.f);
        } else {
            outc[idx] = -oc;            // -center
            outl[idx] = -(mid + rad);   // -upper
            outh[idx] = -(mid - rad);   // -lower
        }
    }
}

// ---------------------------------------------------------------------------
// Host orchestration (graph-capturable).
// ---------------------------------------------------------------------------
static inline int cdiv(int a, int b) { return (a + b - 1) / b; }

extern "C" void kernel_launch(void* const* d_in, const int* in_sizes, int n_in,
                              void* d_out, int out_size)
{
    const float* x   = (const float*)d_in[0];
    const float* lo  = (const float*)d_in[1];
    const float* hi  = (const float*)d_in[2];
    const float* w1  = (const float*)d_in[3];
    const float* w2  = (const float*)d_in[4];
    const float* w3  = (const float*)d_in[5];
    const float* w4  = (const float*)d_in[6];
    const float* w5  = (const float*)d_in[7];
    const float* fw1 = (const float*)d_in[8];
    const float* fw2 = (const float*)d_in[9];
    const float* fw3 = (const float*)d_in[10];
    const float* fb3 = (const float*)d_in[11];
    float* out = (float*)d_out;

    float *A, *Bf, *P, *WP;
    cudaGetSymbolAddress((void**)&A,  g_bufA);
    cudaGetSymbolAddress((void**)&Bf, g_bufB);
    cudaGetSymbolAddress((void**)&P,  g_patch);
    cudaGetSymbolAddress((void**)&WP, g_wpad);
    float *Ac = A,  *Al = A  + VS, *Ah = A  + 2 * VS;
    float *Bc = Bf, *Bl = Bf + VS, *Bh = Bf + 2 * VS;
    float *Pc = P,  *Pl = P  + PS, *Ph = P  + 2 * PS;

#define IM2COL(ic, il, ih, B_, C_, H_, W_, K_, S_, PAD_, HO_, WO_, FP_)            \
    im2col_kernel<<<cdiv((B_) * (HO_) * (WO_) * (FP_), 256), 256>>>(               \
        ic, il, ih, Pc, Pl, Ph, B_, C_, H_, W_, K_, S_, PAD_, HO_, WO_, FP_)

#define CONVP(W_, oc, ol, oh, BL_, O_, FP_, L_)                                    \
    normdist_conv_p_kernel<<<cdiv((BL_) * ((O_) / 4) * 32, 256), 256>>>(           \
        Pc, Pl, Ph, W_, oc, ol, oh, BL_, (O_) / 4, FP_, L_, O_)

    // conv1: [16,3,32,32] -> [16,96,15,15]   (k=7,s=2,p=2), F=147 -> Fp=148
    wpad_kernel<<<cdiv(96 * 148, 256), 256>>>(w1, WP, 96, 147, 148);
    IM2COL(x, lo, hi, 16, 3, 32, 32, 7, 2, 2, 15, 15, 148);
    CONVP(WP, Ac, Al, Ah, 16 * 225, 96, 148, 225);

    // pool1: 15 -> 7
    maxpool_kernel<<<cdiv(16 * 96 * 7 * 7, 256), 256>>>(
        Ac, Al, Ah, Bc, Bl, Bh, 16 * 96, 15, 15, 7, 7);

    // conv2: [16,96,7,7] -> [16,256,7,7]     (k=5,s=1,p=2), F=2400
    IM2COL(Bc, Bl, Bh, 16, 96, 7, 7, 5, 1, 2, 7, 7, 2400);
    CONVP(w2, Ac, Al, Ah, 16 * 49, 256, 2400, 49);

    // pool2: 7 -> 3
    maxpool_kernel<<<cdiv(16 * 256 * 3 * 3, 256), 256>>>(
        Ac, Al, Ah, Bc, Bl, Bh, 16 * 256, 7, 7, 3, 3);

    // conv3: [16,256,3,3] -> [16,384,3,3]    (k=3,s=1,p=1), F=2304
    IM2COL(Bc, Bl, Bh, 16, 256, 3, 3, 3, 1, 1, 3, 3, 2304);
    CONVP(w3, Ac, Al, Ah, 16 * 9, 384, 2304, 9);

    // conv4: [16,384,3,3] -> [16,384,3,3], F=3456
    IM2COL(Ac, Al, Ah, 16, 384, 3, 3, 3, 1, 1, 3, 3, 3456);
    CONVP(w4, Bc, Bl, Bh, 16 * 9, 384, 3456, 9);

    // conv5: [16,384,3,3] -> [16,256,3,3], F=3456
    IM2COL(Bc, Bl, Bh, 16, 384, 3, 3, 3, 1, 1, 3, 3, 3456);
    CONVP(w5, Ac, Al, Ah, 16 * 9, 256, 3456, 9);

    // fc1: 2304 -> 1024 (+relu)
    bound_linear_kernel<<<cdiv(16 * 1024 * 32, 256), 256>>>(
        Ac, Al, Ah, fw1, (const float*)nullptr, Bc, Bl, Bh, 16, 2304, 1024, 0);
    // fc2: 1024 -> 512 (+relu)
    bound_linear_kernel<<<cdiv(16 * 512 * 32, 256), 256>>>(
        Bc, Bl, Bh, fw2, (const float*)nullptr, Ac, Al, Ah, 16, 1024, 512, 0);
    // fc3: 512 -> 10 (+bias), final: d_out = [-c | -u | -l]
    bound_linear_kernel<<<cdiv(16 * 10 * 32, 256), 256>>>(
        Ac, Al, Ah, fw3, fb3, out, out + 160, out + 320, 16, 512, 10, 1);

#undef IM2COL
#undef CONVP
}